// round 7
// baseline (speedup 1.0000x reference)
#include <cuda_runtime.h>
#include <math.h>
#include <stdint.h>

// ---------------------------------------------------------------------------
// Model constants
// ---------------------------------------------------------------------------
#define T_STEPS 800
#define BATCH   128
#define UDIM    64
#define ADIM    64
#define HDIM    256
#define KMIX    10
#define GMIX    20

// Region-padded combined-k layout (k4 = block of 4 k):
//   k4 0        : x (3 real + 1 zero pad)
//   k4 1..16    : w (64)
//   k4 17..80   : h_a (256)   (h1 for L1/L2, h2 for L3)
//   k4 81..144  : h_b (256)   (h2 for L2, h3 for L3)
#define NK4_L1  81
#define NK4_L23 145
#define NTAB (NK4_L1 + 2 * NK4_L23)   // 371

#define NSLICE  8             // gate slices per batch group = cluster size
#define NBATCH  8             // batches per group
#define NGROUPS (BATCH / NBATCH)   // 16
#define UNITS   32            // hidden units per slice
#define RNN_THREADS 256
#define RNN_CTAS (NGROUPS * NSLICE)   // 128 CTAs, one wave

#define HEAD_ROWS 32
#define HEAD_THREADS 128
#define TB_ROWS (T_STEPS * BATCH)

// packed f32x2 helpers (FFMA2 is PTX-only; ptxas never auto-fuses)
#define FMA2(d, a, b, c) \
    asm("fma.rn.f32x2 %0, %1, %2, %3;" : "=l"(d) : "l"(a), "l"(b), "l"(c))
#define PACK2(d, s) \
    asm("mov.b64 %0, {%1, %1};" : "=l"(d) : "r"(__float_as_uint(s)))

#define CLUSTER_SYNC() do { \
    asm volatile("barrier.cluster.arrive.aligned;" ::: "memory"); \
    asm volatile("barrier.cluster.wait.aligned;" ::: "memory"); \
} while (0)

__device__ __forceinline__ uint32_t smem_u32(const void* p) {
    return (uint32_t)__cvta_generic_to_shared(p);
}
// store one float4 into the SAME smem offset of CTA `rank` in this cluster
__device__ __forceinline__ void push_f4(uint32_t laddr, int rank, float4 v) {
    uint32_t ra;
    asm volatile("mapa.shared::cluster.u32 %0, %1, %2;"
                 : "=r"(ra) : "r"(laddr), "r"(rank));
    asm volatile("st.shared::cluster.v4.b32 [%0], {%1, %2, %3, %4};"
                 :: "r"(ra), "r"(__float_as_uint(v.x)), "r"(__float_as_uint(v.y)),
                    "r"(__float_as_uint(v.z)), "r"(__float_as_uint(v.w))
                 : "memory");
}

// ---------------------------------------------------------------------------
// Device scratch (static __device__ — no allocations allowed)
// ---------------------------------------------------------------------------
__device__ float g_W1[NSLICE * NK4_L1  * 512];   // [slice][k4][m][kk]
__device__ float g_W2[NSLICE * NK4_L23 * 512];
__device__ float g_W3[NSLICE * NK4_L23 * 512];
__device__ float g_B[3 * NSLICE * 128];
__device__ float g_WHt[HDIM * 128];
__device__ float g_bh[128];
__device__ float g_h3buf[(size_t)T_STEPS * BATCH * HDIM];

// ---------------------------------------------------------------------------
// Prologue kernels
// ---------------------------------------------------------------------------
// Weight layout: dst[r][k4][m][kk]; row = (m>>5)*256 + r*32 + (m&31); k = 4*k4+kk
// region-padded k mapping (see top).
__global__ void build_ws_kernel(const float* __restrict__ Wih,
                                const float* __restrict__ Whh,
                                int nk4, int layer) {
    int idx = blockIdx.x * blockDim.x + threadIdx.x;
    int per = nk4 * 512;
    if (idx >= NSLICE * per) return;
    int r   = idx / per;
    int rem = idx % per;
    int k4  = rem >> 9;
    int q   = rem & 511;
    int m   = q >> 2;
    int kk  = q & 3;
    int k   = k4 * 4 + kk;
    int row = (m >> 5) * 256 + r * UNITS + (m & 31);
    float v = 0.0f;
    if (layer == 0) {           // IN = 67
        if (k < 3)                 v = Wih[row * 67 + k];
        else if (k >= 4 && k < 68) v = Wih[row * 67 + (k - 1)];
        else if (k >= 68)          v = Whh[row * HDIM + (k - 68)];
    } else {                    // IN = 323
        if (k < 3)                  v = Wih[row * 323 + k];
        else if (k >= 4 && k < 324) v = Wih[row * 323 + (k - 1)];
        else if (k >= 324)          v = Whh[row * HDIM + (k - 324)];
    }
    float* dst = (layer == 0) ? g_W1 : (layer == 1) ? g_W2 : g_W3;
    dst[idx] = v;
}

__global__ void build_bias_kernel(const float* b1, const float* b2, const float* b3) {
    int idx = blockIdx.x * blockDim.x + threadIdx.x;
    if (idx >= 3 * NSLICE * 128) return;
    int layer = idx / (NSLICE * 128);
    int rem   = idx % (NSLICE * 128);
    int r     = rem / 128;
    int m     = rem % 128;
    int row   = (m >> 5) * 256 + r * UNITS + (m & 31);
    const float* b = (layer == 0) ? b1 : (layer == 1) ? b2 : b3;
    g_B[idx] = b[row];
}

__global__ void build_head_kernel(const float* We,  const float* be,
                                  const float* Wpi, const float* bpi,
                                  const float* Wm1, const float* bm1,
                                  const float* Wm2, const float* bm2,
                                  const float* Ws1, const float* bs1,
                                  const float* Ws2, const float* bs2,
                                  const float* Wr,  const float* br) {
    int idx = blockIdx.x * blockDim.x + threadIdx.x;
    if (idx >= HDIM * 128) return;
    int k = idx >> 7;
    int o = idx & 127;
    const float* W = nullptr; const float* bb = nullptr; int row = 0;
    if (o == 0)        { W = We;  bb = be;  row = 0; }
    else if (o <= 20)  { W = Wpi; bb = bpi; row = o - 1; }
    else if (o <= 40)  { W = Wm1; bb = bm1; row = o - 21; }
    else if (o <= 60)  { W = Wm2; bb = bm2; row = o - 41; }
    else if (o <= 80)  { W = Ws1; bb = bs1; row = o - 61; }
    else if (o <= 100) { W = Ws2; bb = bs2; row = o - 81; }
    else if (o <= 120) { W = Wr;  bb = br;  row = o - 101; }
    g_WHt[k * 128 + o] = W ? W[row * HDIM + k] : 0.0f;
    if (k == 0) g_bh[o] = bb ? bb[row] : 0.0f;
}

// ---------------------------------------------------------------------------
// Recurrent kernel smem
// ---------------------------------------------------------------------------
struct __align__(16) SmemR {
    float zpart[8 * 128 * NBATCH];   // per-warp GEMV partials  (32 KB)
    float z[128 * NBATCH];           // reduced gates [m][b]
    float pub_h1[2][HDIM * NBATCH];  // [parity][u*8+b]  peers push slices here
    float pub_h2[2][HDIM * NBATCH];
    float pub_h3[2][HDIM * NBATCH];
    float pub_w[2][ADIM * NBATCH];   // [parity][a*8+b]
    float pubwin[NSLICE * 240];      // win partial dots [rank][o*8+b]
    float hloc[UNITS * NBATCH];      // this CTA's fresh h slice [u*8+b]
    float wloc[64];                  // this CTA's w slice [a*8+b]
    float Ploc[240];                 // local win partials [o*8+b]
    float xpad[4 * NBATCH];          // x block (k4 0), slot k=3 stays 0
    float cm[UDIM * 64];             // attention memory [u][b*8+a]
    float WwS[30 * 33 + 2];          // Ww slice [o][u in my 32], padded stride 33
    float bws[32];
    float b1s[128], b2s[128], b3s[128];
    float atts[32 * NBATCH];         // exp(win) [o*8+b]
    float kappas[KMIX * NBATCH];
    float phis[UDIM * NBATCH];
    float c1[UNITS * NBATCH], c2[UNITS * NBATCH], c3[UNITS * NBATCH];
    const float* tab[2][NTAB];       // per-parity k4 -> smem region pointer
};

__device__ __forceinline__ float sigm(float v) { return 1.0f / (1.0f + __expf(-v)); }

// k-sliced GEMV, strided k4 ownership: warp w handles k4 = w, w+8, ...
// Lane owns m = {lane, lane+32, lane+64, lane+96}, 8 batches as 4 f32x2.
__device__ __forceinline__ void gemv_ws(const float* __restrict__ W,
                                        const float* const* __restrict__ vtab,
                                        float* __restrict__ zpart, int nk4) {
    const int lane = threadIdx.x & 31;
    const int warp = threadIdx.x >> 5;

    unsigned long long acc[4][4];
#pragma unroll
    for (int j = 0; j < 4; ++j)
#pragma unroll
        for (int p = 0; p < 4; ++p) acc[j][p] = 0ULL;

    const float4* W4 = (const float4*)W;
    int k4 = warp;
    float4 w0, w1, w2, w3;
    const float* vp = vtab[0];
    if (k4 < nk4) {
        const float4* Wp = W4 + (size_t)k4 * 128 + lane;
        w0 = Wp[0]; w1 = Wp[32]; w2 = Wp[64]; w3 = Wp[96];
        vp = vtab[k4];
    }
    while (k4 < nk4) {
        float4 cw[4] = { w0, w1, w2, w3 };
        const float* cvp = vp;
        int kn = k4 + 8;
        if (kn < nk4) {
            const float4* Wp = W4 + (size_t)kn * 128 + lane;
            w0 = Wp[0]; w1 = Wp[32]; w2 = Wp[64]; w3 = Wp[96];
            vp = vtab[kn];
        }
        const ulonglong2* V = (const ulonglong2*)cvp;
#pragma unroll
        for (int kk = 0; kk < 4; ++kk) {
            ulonglong2 va = V[kk * 2];
            ulonglong2 vb = V[kk * 2 + 1];
#pragma unroll
            for (int j = 0; j < 4; ++j) {
                float wjk = ((const float*)&cw[j])[kk];
                unsigned long long wp;
                PACK2(wp, wjk);
                FMA2(acc[j][0], wp, va.x, acc[j][0]);
                FMA2(acc[j][1], wp, va.y, acc[j][1]);
                FMA2(acc[j][2], wp, vb.x, acc[j][2]);
                FMA2(acc[j][3], wp, vb.y, acc[j][3]);
            }
        }
        k4 = kn;
    }
#pragma unroll
    for (int j = 0; j < 4; ++j) {
        int m = lane + 32 * j;
        unsigned long long* zp = (unsigned long long*)&zpart[(warp * 128 + m) * NBATCH];
#pragma unroll
        for (int p = 0; p < 4; ++p) zp[p] = acc[j][p];
    }
}

__device__ __forceinline__ void gemv_reduce(const float* __restrict__ zpart,
                                            const float* __restrict__ bias,
                                            float* __restrict__ z) {
    const int tid = threadIdx.x;
    const int m = tid >> 1, q = tid & 1;
    float b = bias[m];
    float4 acc = make_float4(b, b, b, b);
#pragma unroll
    for (int w = 0; w < 8; ++w) {
        float4 p = *(const float4*)&zpart[(w * 128 + m) * NBATCH + q * 4];
        acc.x += p.x; acc.y += p.y; acc.z += p.z; acc.w += p.w;
    }
    *(float4*)&z[m * NBATCH + q * 4] = acc;
}

// LSTM cell for this slice's 32 units x 8 batches; stages h into hloc
__device__ __forceinline__ float cell_update(const float* __restrict__ z,
                                             float* __restrict__ c_s,
                                             float* __restrict__ hloc) {
    const int tid = threadIdx.x;
    const int u = tid >> 3, b = tid & 7;
    float zi = z[(u)      * NBATCH + b];
    float zf = z[(32 + u) * NBATCH + b];
    float zg = z[(64 + u) * NBATCH + b];
    float zo = z[(96 + u) * NBATCH + b];
    float c  = sigm(zf) * c_s[tid] + sigm(zi) * tanhf(zg);
    c_s[tid] = c;
    float h  = sigm(zo) * tanhf(c);
    hloc[u * 8 + b] = h;
    return h;
}

extern __shared__ char smem_raw[];

__global__ void __launch_bounds__(RNN_THREADS, 1) __cluster_dims__(NSLICE, 1, 1)
rnn_kernel(const float* __restrict__ x,    // [T, B, 3]
           const float* __restrict__ cg,   // [B, U, A]
           const float* __restrict__ Ww,   // [30, 256]
           const float* __restrict__ bw)   // [30]
{
    SmemR* s = (SmemR*)smem_raw;
    const int tid = threadIdx.x;
    uint32_t rr;
    asm("mov.u32 %0, %%cluster_ctarank;" : "=r"(rr));
    const int r  = (int)rr;              // gate slice 0..7
    const int g  = blockIdx.x >> 3;      // batch group 0..15
    const int b0 = g * NBATCH;

    // ---- init ----
    for (int i = tid; i < 30 * 32; i += RNN_THREADS) {
        int o = i >> 5, u = i & 31;
        s->WwS[o * 33 + u] = Ww[o * 256 + r * UNITS + u];
    }
    if (tid < 32) s->bws[tid] = (tid < 30) ? bw[tid] : 0.0f;
    if (tid < 128) {
        s->b1s[tid] = g_B[(0 * NSLICE + r) * 128 + tid];
        s->b2s[tid] = g_B[(1 * NSLICE + r) * 128 + tid];
        s->b3s[tid] = g_B[(2 * NSLICE + r) * 128 + tid];
    }
    for (int i = tid; i < UDIM * 64; i += RNN_THREADS) {
        int u = i >> 6, q = i & 63, b = q >> 3, a = q & 7;
        s->cm[i] = cg[(size_t)(b0 + b) * (UDIM * ADIM) + u * ADIM + (r * 8 + a)];
    }
    for (int i = tid; i < HDIM * NBATCH; i += RNN_THREADS) {
        s->pub_h1[0][i] = 0.0f; s->pub_h1[1][i] = 0.0f;
        s->pub_h2[0][i] = 0.0f; s->pub_h2[1][i] = 0.0f;
        s->pub_h3[0][i] = 0.0f; s->pub_h3[1][i] = 0.0f;
    }
    for (int i = tid; i < ADIM * NBATCH; i += RNN_THREADS) {
        s->pub_w[0][i] = 1.0f; s->pub_w[1][i] = 1.0f;
    }
    if (tid < 32) s->xpad[tid] = 0.0f;
    s->c1[tid] = 0.0f; s->c2[tid] = 0.0f; s->c3[tid] = 0.0f;
    if (tid < KMIX * NBATCH) s->kappas[tid] = 0.0f;

    // pointer tables (per write-parity pw; pr = pw^1 holds previous-step values)
    for (int i = tid; i < 2 * NTAB; i += RNN_THREADS) {
        int pw = i / NTAB, j = i % NTAB;
        int pr = pw ^ 1;
        int layer, k4;
        if (j < NK4_L1)                { layer = 0; k4 = j; }
        else if (j < NK4_L1 + NK4_L23) { layer = 1; k4 = j - NK4_L1; }
        else                           { layer = 2; k4 = j - NK4_L1 - NK4_L23; }
        const float* p;
        if (k4 == 0)       p = s->xpad;
        else if (k4 < 17)  p = &s->pub_w[layer == 0 ? pr : pw][(k4 - 1) * 32];
        else if (k4 < 81) {
            if (layer == 0)      p = &s->pub_h1[pr][(k4 - 17) * 32];
            else if (layer == 1) p = &s->pub_h1[pw][(k4 - 17) * 32];
            else                 p = &s->pub_h2[pw][(k4 - 17) * 32];
        } else {
            if (layer == 1)      p = &s->pub_h2[pr][(k4 - 81) * 32];
            else                 p = &s->pub_h3[pr][(k4 - 81) * 32];
        }
        s->tab[pw][j] = p;
    }
    __syncthreads();
    CLUSTER_SYNC();

    const float* W1 = g_W1 + r * (NK4_L1  * 512);
    const float* W2 = g_W2 + r * (NK4_L23 * 512);
    const float* W3 = g_W3 + r * (NK4_L23 * 512);

    const uint32_t a_pubh1 = smem_u32(&s->pub_h1[0][0]);
    const uint32_t a_pubh2 = smem_u32(&s->pub_h2[0][0]);
    const uint32_t a_pubh3 = smem_u32(&s->pub_h3[0][0]);
    const uint32_t a_pubw  = smem_u32(&s->pub_w[0][0]);
    const uint32_t a_pwin  = smem_u32(&s->pubwin[0]);
    const uint32_t PUBH_PAR = HDIM * NBATCH * 4;   // bytes per parity
    const uint32_t PUBW_PAR = ADIM * NBATCH * 4;

    for (int t = 0; t < T_STEPS; ++t) {
        const int pw = t & 1;
        const float* const* tabL1 = s->tab[pw];
        const float* const* tabL2 = s->tab[pw] + NK4_L1;
        const float* const* tabL3 = s->tab[pw] + NK4_L1 + NK4_L23;

        if (tid < 24) {
            int b = tid / 3, k = tid % 3;
            s->xpad[k * 8 + b] = x[((size_t)t * BATCH + b0 + b) * 3 + k];
        }
        __syncthreads();

        // ================= layer 1 =================
        gemv_ws(W1, tabL1, s->zpart, NK4_L1);
        __syncthreads();
        gemv_reduce(s->zpart, s->b1s, s->z);
        __syncthreads();
        cell_update(s->z, s->c1, s->hloc);
        __syncthreads();

        // win partial dots over MY 32 h1 units, and push my h1 slice
        if (tid < 240) {
            int o = tid >> 3, b = tid & 7;
            float acc = 0.0f;
#pragma unroll 8
            for (int u = 0; u < 32; ++u)
                acc = fmaf(s->WwS[o * 33 + u], s->hloc[u * 8 + b], acc);
            s->Ploc[o * 8 + b] = acc;
        }
        {
            const float4* hl4 = (const float4*)s->hloc;
#pragma unroll
            for (int i = 0; i < 2; ++i) {
                int q = tid + i * 256;
                int rk = q >> 6, f4 = q & 63;
                push_f4(a_pubh1 + pw * PUBH_PAR + (uint32_t)(r * 64 + f4) * 16, rk, hl4[f4]);
            }
        }
        __syncthreads();
        {
            const float4* P4 = (const float4*)s->Ploc;
#pragma unroll
            for (int i = 0; i < 2; ++i) {
                int q = tid + i * 256;
                if (q < 480) {
                    int rk = q / 60, f4 = q % 60;
                    push_f4(a_pwin + (uint32_t)(r * 60 + f4) * 16, rk, P4[f4]);
                }
            }
        }
        CLUSTER_SYNC();   // bar0: h1 + win partials delivered everywhere

        // ---- attention (replicated per CTA) ----
        if (tid < 240) {
            int o = tid >> 3, b = tid & 7;
            float sum = s->bws[o];
#pragma unroll
            for (int rk = 0; rk < NSLICE; ++rk) sum += s->pubwin[rk * 240 + o * 8 + b];
            s->atts[o * 8 + b] = __expf(sum);
        }
        __syncthreads();
        if (tid < KMIX * NBATCH) {
            int kk = tid >> 3, b = tid & 7;
            s->kappas[tid] += 0.1f * s->atts[(20 + kk) * 8 + b];
        }
        __syncthreads();
        for (int i = tid; i < UDIM * NBATCH; i += RNN_THREADS) {
            int u = i >> 3, b = i & 7;
            float uu = (float)u;
            float acc = 0.0f;
#pragma unroll
            for (int kk = 0; kk < KMIX; ++kk) {
                float d = s->kappas[kk * 8 + b] - uu;
                acc = fmaf(s->atts[kk * 8 + b],
                           __expf(-s->atts[(10 + kk) * 8 + b] * d * d), acc);
            }
            s->phis[i] = acc;
        }
        __syncthreads();
        if (tid < 64) {   // my 8-wide a-slice of w, all 8 batches
            int b = tid >> 3, a = tid & 7;
            float acc = 0.0f;
#pragma unroll 8
            for (int u = 0; u < UDIM; ++u)
                acc = fmaf(s->phis[u * 8 + b], s->cm[u * 64 + b * 8 + a], acc);
            s->wloc[a * 8 + b] = acc;
        }
        __syncthreads();
        if (tid < 128) {
            int rk = tid >> 4, f4 = tid & 15;
            float4 v = ((const float4*)s->wloc)[f4];
            push_f4(a_pubw + pw * PUBW_PAR + (uint32_t)(r * 16 + f4) * 16, rk, v);
        }
        CLUSTER_SYNC();   // bar1: w delivered

        // ================= layer 2 =================
        gemv_ws(W2, tabL2, s->zpart, NK4_L23);
        __syncthreads();
        gemv_reduce(s->zpart, s->b2s, s->z);
        __syncthreads();
        cell_update(s->z, s->c2, s->hloc);
        __syncthreads();
        {
            const float4* hl4 = (const float4*)s->hloc;
#pragma unroll
            for (int i = 0; i < 2; ++i) {
                int q = tid + i * 256;
                int rk = q >> 6, f4 = q & 63;
                push_f4(a_pubh2 + pw * PUBH_PAR + (uint32_t)(r * 64 + f4) * 16, rk, hl4[f4]);
            }
        }
        CLUSTER_SYNC();   // bar2: h2 delivered

        // ================= layer 3 =================
        gemv_ws(W3, tabL3, s->zpart, NK4_L23);
        __syncthreads();
        gemv_reduce(s->zpart, s->b3s, s->z);
        __syncthreads();
        {
            float h = cell_update(s->z, s->c3, s->hloc);
            int u = tid >> 3, b = tid & 7;
            g_h3buf[((size_t)t * BATCH + b0 + b) * HDIM + r * UNITS + u] = h;
        }
        __syncthreads();
        {
            const float4* hl4 = (const float4*)s->hloc;
#pragma unroll
            for (int i = 0; i < 2; ++i) {
                int q = tid + i * 256;
                int rk = q >> 6, f4 = q & 63;
                push_f4(a_pubh3 + pw * PUBH_PAR + (uint32_t)(r * 64 + f4) * 16, rk, hl4[f4]);
            }
        }
        CLUSTER_SYNC();   // bar3: h3 delivered
    }
}

// ---------------------------------------------------------------------------
// Output head
// ---------------------------------------------------------------------------
__global__ void __launch_bounds__(HEAD_THREADS)
head_kernel(float* __restrict__ out) {
    __shared__ float sh[HEAD_ROWS * HDIM];
    const int tid = threadIdx.x;
    const int r0  = blockIdx.x * HEAD_ROWS;

    for (int i = tid; i < HEAD_ROWS * HDIM; i += HEAD_THREADS)
        sh[i] = g_h3buf[(size_t)r0 * HDIM + i];
    __syncthreads();

    float acc[HEAD_ROWS];
    float bias = g_bh[tid];
#pragma unroll
    for (int r = 0; r < HEAD_ROWS; ++r) acc[r] = bias;

    for (int k = 0; k < HDIM; k += 4) {
        float w0 = g_WHt[(k + 0) * 128 + tid];
        float w1 = g_WHt[(k + 1) * 128 + tid];
        float w2 = g_WHt[(k + 2) * 128 + tid];
        float w3 = g_WHt[(k + 3) * 128 + tid];
#pragma unroll
        for (int r = 0; r < HEAD_ROWS; ++r) {
            float4 hv = *(const float4*)&sh[r * HDIM + k];
            acc[r] = fmaf(hv.x, w0, fmaf(hv.y, w1, fmaf(hv.z, w2, fmaf(hv.w, w3, acc[r]))));
        }
    }
    __syncthreads();

    float* so = sh;
    if (tid < 121) {
#pragma unroll
        for (int r = 0; r < HEAD_ROWS; ++r) so[r * 129 + tid] = acc[r];
    }
    __syncthreads();

    if (tid < HEAD_ROWS) {
        float m = -1e30f;
#pragma unroll
        for (int g = 0; g < GMIX; ++g) m = fmaxf(m, so[tid * 129 + 1 + g]);
        float e[GMIX]; float ssum = 0.0f;
#pragma unroll
        for (int g = 0; g < GMIX; ++g) { e[g] = expf(so[tid * 129 + 1 + g] - m); ssum += e[g]; }
        float inv = 1.0f / ssum;
#pragma unroll
        for (int g = 0; g < GMIX; ++g) so[tid * 129 + 1 + g] = e[g] * inv;
    }
    __syncthreads();

    const size_t TB  = (size_t)TB_ROWS;
    const size_t TBG = TB * GMIX;
    float* es  = out;
    float* pis = out + TB;
    float* mu1 = pis + TBG;
    float* mu2 = mu1 + TBG;
    float* s1  = mu2 + TBG;
    float* s2  = s1 + TBG;
    float* rho = s2 + TBG;

    if (tid < HEAD_ROWS)
        es[r0 + tid] = 1.0f / (1.0f + expf(so[tid * 129 + 0]));

    for (int idx = tid; idx < HEAD_ROWS * GMIX; idx += HEAD_THREADS) {
        int r = idx / GMIX, g = idx % GMIX;
        size_t off = (size_t)(r0 + r) * GMIX + g;
        pis[off] = so[r * 129 + 1 + g];
        mu1[off] = so[r * 129 + 21 + g];
        mu2[off] = so[r * 129 + 41 + g];
        s1[off]  = expf(so[r * 129 + 61 + g]);
        s2[off]  = expf(so[r * 129 + 81 + g]);
        rho[off] = tanhf(so[r * 129 + 101 + g]);
    }
}

// ---------------------------------------------------------------------------
// Launch
// ---------------------------------------------------------------------------
extern "C" void kernel_launch(void* const* d_in, const int* in_sizes, int n_in,
                              void* d_out, int out_size) {
    (void)in_sizes; (void)n_in; (void)out_size;
    const float* x     = (const float*)d_in[0];
    const float* cg    = (const float*)d_in[1];
    const float* W1ih  = (const float*)d_in[2];
    const float* W1hh  = (const float*)d_in[3];
    const float* b1    = (const float*)d_in[4];
    const float* W2ih  = (const float*)d_in[5];
    const float* W2hh  = (const float*)d_in[6];
    const float* b2    = (const float*)d_in[7];
    const float* W3ih  = (const float*)d_in[8];
    const float* W3hh  = (const float*)d_in[9];
    const float* b3    = (const float*)d_in[10];
    const float* Ww    = (const float*)d_in[11];
    const float* bw    = (const float*)d_in[12];
    const float* We    = (const float*)d_in[13];
    const float* be    = (const float*)d_in[14];
    const float* Wpi   = (const float*)d_in[15];
    const float* bpi   = (const float*)d_in[16];
    const float* Wm1   = (const float*)d_in[17];
    const float* bm1   = (const float*)d_in[18];
    const float* Wm2   = (const float*)d_in[19];
    const float* bm2   = (const float*)d_in[20];
    const float* Ws1   = (const float*)d_in[21];
    const float* bs1   = (const float*)d_in[22];
    const float* Ws2   = (const float*)d_in[23];
    const float* bs2   = (const float*)d_in[24];
    const float* Wr    = (const float*)d_in[25];
    const float* br    = (const float*)d_in[26];

    build_ws_kernel<<<(NSLICE * NK4_L1  * 512 + 255) / 256, 256>>>(W1ih, W1hh, NK4_L1, 0);
    build_ws_kernel<<<(NSLICE * NK4_L23 * 512 + 255) / 256, 256>>>(W2ih, W2hh, NK4_L23, 1);
    build_ws_kernel<<<(NSLICE * NK4_L23 * 512 + 255) / 256, 256>>>(W3ih, W3hh, NK4_L23, 2);
    build_bias_kernel<<<(3 * NSLICE * 128 + 255) / 256, 256>>>(b1, b2, b3);
    build_head_kernel<<<(HDIM * 128 + 255) / 256, 256>>>(We, be, Wpi, bpi, Wm1, bm1,
                                                         Wm2, bm2, Ws1, bs1, Ws2, bs2, Wr, br);

    static bool attr_set = false;
    int smem_bytes = (int)sizeof(SmemR);
    if (!attr_set) {
        cudaFuncSetAttribute(rnn_kernel, cudaFuncAttributeMaxDynamicSharedMemorySize,
                             smem_bytes);
        attr_set = true;
    }
    rnn_kernel<<<RNN_CTAS, RNN_THREADS, smem_bytes>>>(x, cg, Ww, bw);

    head_kernel<<<TB_ROWS / HEAD_ROWS, HEAD_THREADS>>>((float*)d_out);
}

// round 8
// speedup vs baseline: 1.8565x; 1.8565x over previous
#include <cuda_runtime.h>
#include <math.h>
#include <stdint.h>

// ---------------------------------------------------------------------------
// Model constants
// ---------------------------------------------------------------------------
#define T_STEPS 800
#define BATCH   128
#define UDIM    64
#define ADIM    64
#define HDIM    256
#define KMIX    10
#define GMIX    20

// Region-padded combined-k layout (k4 = block of 4 k):
//   k4 0        : x (3 real + 1 zero pad)
//   k4 1..16    : w (64)
//   k4 17..80   : h_a (256)   (h1 for L1/L2, h2 for L3)
//   k4 81..144  : h_b (256)   (h2 for L2, h3 for L3)
#define NK4_L1  81
#define NK4_L23 145
#define NTAB (NK4_L1 + 2 * NK4_L23)   // 371

#define NSLICE  8             // gate slices per batch group
#define NBATCH  8             // batches per group
#define NGROUPS (BATCH / NBATCH)   // 16
#define UNITS   32            // hidden units per slice
#define RNN_THREADS 256
#define RNN_CTAS (NGROUPS * NSLICE)   // 128 CTAs, one wave

#define HEAD_ROWS 32
#define HEAD_THREADS 128
#define TB_ROWS (T_STEPS * BATCH)

// packed f32x2 helpers (FFMA2 is PTX-only; ptxas never auto-fuses)
#define FMA2(d, a, b, c) \
    asm("fma.rn.f32x2 %0, %1, %2, %3;" : "=l"(d) : "l"(a), "l"(b), "l"(c))
#define PACK2(d, s) \
    asm("mov.b64 %0, {%1, %1};" : "=l"(d) : "r"(__float_as_uint(s)))

// ---------------------------------------------------------------------------
// Device scratch (static __device__ — no allocations allowed)
// ---------------------------------------------------------------------------
__device__ float g_W1[NSLICE * NK4_L1  * 512];   // [slice][k4][m][kk]
__device__ float g_W2[NSLICE * NK4_L23 * 512];
__device__ float g_W3[NSLICE * NK4_L23 * 512];
__device__ float g_B[3 * NSLICE * 128];
__device__ float g_pubh[3][2][NGROUPS][HDIM * NBATCH];  // h exchange [layer][parity][g][u*8+b]
__device__ float g_wx[NGROUPS][ADIM * NBATCH];          // w exchange [a*8+b] (single buffer)
__device__ float g_pwin[NGROUPS][NSLICE * 240];         // win partials [g][r*240 + o*8+b]
__device__ float g_xt[(size_t)T_STEPS * NGROUPS * 32];  // x transposed [t][g][k*8+b], k=3 pad 0
__device__ int   g_flags[NGROUPS * T_STEPS * 4];
__device__ float g_WHt[HDIM * 128];
__device__ float g_bh[128];
__device__ float g_h3buf[(size_t)T_STEPS * BATCH * HDIM];

// ---------------------------------------------------------------------------
// Prologue kernels
// ---------------------------------------------------------------------------
__global__ void init_bufs_kernel(const float* __restrict__ x) {
    int stride = gridDim.x * blockDim.x;
    int i0 = blockIdx.x * blockDim.x + threadIdx.x;
    float* ph = &g_pubh[0][0][0][0];
    for (int i = i0; i < 3 * 2 * NGROUPS * HDIM * NBATCH; i += stride) ph[i] = 0.0f;
    float* pw = &g_wx[0][0];
    for (int i = i0; i < NGROUPS * ADIM * NBATCH; i += stride) pw[i] = 1.0f;
    float* pp = &g_pwin[0][0];
    for (int i = i0; i < NGROUPS * NSLICE * 240; i += stride) pp[i] = 0.0f;
    for (int i = i0; i < NGROUPS * T_STEPS * 4; i += stride) g_flags[i] = 0;
    for (int i = i0; i < T_STEPS * NGROUPS * 32; i += stride) {
        int t = i >> 9, rem = i & 511;
        int g = rem >> 5, q = rem & 31;
        int k = q >> 3, b = q & 7;
        g_xt[i] = (k < 3) ? x[((size_t)t * BATCH + g * 8 + b) * 3 + k] : 0.0f;
    }
}

// Weight layout: dst[r][k4][m][kk]; row = (m>>5)*256 + r*32 + (m&31); k = 4*k4+kk
__global__ void build_ws_kernel(const float* __restrict__ Wih,
                                const float* __restrict__ Whh,
                                int nk4, int layer) {
    int idx = blockIdx.x * blockDim.x + threadIdx.x;
    int per = nk4 * 512;
    if (idx >= NSLICE * per) return;
    int r   = idx / per;
    int rem = idx % per;
    int k4  = rem >> 9;
    int q   = rem & 511;
    int m   = q >> 2;
    int kk  = q & 3;
    int k   = k4 * 4 + kk;
    int row = (m >> 5) * 256 + r * UNITS + (m & 31);
    float v = 0.0f;
    if (layer == 0) {           // IN = 67
        if (k < 3)                 v = Wih[row * 67 + k];
        else if (k >= 4 && k < 68) v = Wih[row * 67 + (k - 1)];
        else if (k >= 68)          v = Whh[row * HDIM + (k - 68)];
    } else {                    // IN = 323
        if (k < 3)                  v = Wih[row * 323 + k];
        else if (k >= 4 && k < 324) v = Wih[row * 323 + (k - 1)];
        else if (k >= 324)          v = Whh[row * HDIM + (k - 324)];
    }
    float* dst = (layer == 0) ? g_W1 : (layer == 1) ? g_W2 : g_W3;
    dst[idx] = v;
}

__global__ void build_bias_kernel(const float* b1, const float* b2, const float* b3) {
    int idx = blockIdx.x * blockDim.x + threadIdx.x;
    if (idx >= 3 * NSLICE * 128) return;
    int layer = idx / (NSLICE * 128);
    int rem   = idx % (NSLICE * 128);
    int r     = rem / 128;
    int m     = rem % 128;
    int row   = (m >> 5) * 256 + r * UNITS + (m & 31);
    const float* b = (layer == 0) ? b1 : (layer == 1) ? b2 : b3;
    g_B[idx] = b[row];
}

__global__ void build_head_kernel(const float* We,  const float* be,
                                  const float* Wpi, const float* bpi,
                                  const float* Wm1, const float* bm1,
                                  const float* Wm2, const float* bm2,
                                  const float* Ws1, const float* bs1,
                                  const float* Ws2, const float* bs2,
                                  const float* Wr,  const float* br) {
    int idx = blockIdx.x * blockDim.x + threadIdx.x;
    if (idx >= HDIM * 128) return;
    int k = idx >> 7;
    int o = idx & 127;
    const float* W = nullptr; const float* bb = nullptr; int row = 0;
    if (o == 0)        { W = We;  bb = be;  row = 0; }
    else if (o <= 20)  { W = Wpi; bb = bpi; row = o - 1; }
    else if (o <= 40)  { W = Wm1; bb = bm1; row = o - 21; }
    else if (o <= 60)  { W = Wm2; bb = bm2; row = o - 41; }
    else if (o <= 80)  { W = Ws1; bb = bs1; row = o - 61; }
    else if (o <= 100) { W = Ws2; bb = bs2; row = o - 81; }
    else if (o <= 120) { W = Wr;  bb = br;  row = o - 101; }
    g_WHt[k * 128 + o] = W ? W[row * HDIM + k] : 0.0f;
    if (k == 0) g_bh[o] = bb ? bb[row] : 0.0f;
}

// ---------------------------------------------------------------------------
// Recurrent kernel smem
// ---------------------------------------------------------------------------
struct __align__(16) SmemR {
    float zpart[8 * 128 * NBATCH];   // per-warp GEMV partials (32 KB)
    float z[128 * NBATCH];           // reduced gates [m][b]
    float hloc[UNITS * NBATCH];      // this CTA's fresh h slice [u*8+b]
    float wloc[64];                  // this CTA's w slice [a'*8+b]
    float Ploc[240];                 // local win partials [o*8+b]
    float cm[UDIM * 64];             // attention memory [u][b*8+a']
    float WwS[30 * 33 + 2];          // Ww slice [o][my 32 u], stride 33
    float bws[32];
    float b1s[128], b2s[128], b3s[128];
    float atts[32 * NBATCH];         // exp(win) [o*8+b]
    float kappas[KMIX * NBATCH];
    float phis[UDIM * NBATCH];
    float c1[UNITS * NBATCH], c2[UNITS * NBATCH], c3[UNITS * NBATCH];
    const float* tab[2][NTAB];       // per-parity k4 -> GLOBAL region pointer
};

__device__ __forceinline__ float sigm(float v) { return 1.0f / (1.0f + __expf(-v)); }

// flag-based group barrier through L2 (no clusters: cluster.sync flushes L1D)
__device__ __forceinline__ void group_barrier(int g, int t, int site) {
    __threadfence();
    __syncthreads();
    if (threadIdx.x == 0) {
        int* f = &g_flags[((g * T_STEPS) + t) * 4 + site];
        atomicAdd(f, 1);
        while (*((volatile int*)f) < NSLICE) { }
    }
    __syncthreads();
}

// k-sliced GEMV: warp w owns k4 = w, w+8, ... ; vin read straight from GLOBAL
// exchange buffers via __ldcg (uniform broadcast addresses). Depth-2 pipeline
// on both weights (L2) and vin (L2).
__device__ __forceinline__ void gemv_ws(const float* __restrict__ W,
                                        const float* const* __restrict__ vtab,
                                        float* __restrict__ zpart, int nk4) {
    const int lane = threadIdx.x & 31;
    const int warp = threadIdx.x >> 5;

    unsigned long long acc[4][4];
#pragma unroll
    for (int j = 0; j < 4; ++j)
#pragma unroll
        for (int p = 0; p < 4; ++p) acc[j][p] = 0ULL;

    const float4* W4 = (const float4*)W;
    int k4 = warp;
    float4 w0, w1, w2, w3;
    ulonglong2 v[8];
    if (k4 < nk4) {
        const float4* Wp = W4 + (size_t)k4 * 128 + lane;
        w0 = Wp[0]; w1 = Wp[32]; w2 = Wp[64]; w3 = Wp[96];
        const ulonglong2* V = (const ulonglong2*)vtab[k4];
#pragma unroll
        for (int j = 0; j < 8; ++j) v[j] = __ldcg(V + j);
    }
    while (k4 < nk4) {
        float4 cw[4] = { w0, w1, w2, w3 };
        ulonglong2 cv[8];
#pragma unroll
        for (int j = 0; j < 8; ++j) cv[j] = v[j];
        int kn = k4 + 8;
        if (kn < nk4) {
            const float4* Wp = W4 + (size_t)kn * 128 + lane;
            w0 = Wp[0]; w1 = Wp[32]; w2 = Wp[64]; w3 = Wp[96];
            const ulonglong2* V = (const ulonglong2*)vtab[kn];
#pragma unroll
            for (int j = 0; j < 8; ++j) v[j] = __ldcg(V + j);
        }
#pragma unroll
        for (int kk = 0; kk < 4; ++kk) {
            ulonglong2 va = cv[2 * kk], vb = cv[2 * kk + 1];
#pragma unroll
            for (int j = 0; j < 4; ++j) {
                float wjk = ((const float*)&cw[j])[kk];
                unsigned long long wp;
                PACK2(wp, wjk);
                FMA2(acc[j][0], wp, va.x, acc[j][0]);
                FMA2(acc[j][1], wp, va.y, acc[j][1]);
                FMA2(acc[j][2], wp, vb.x, acc[j][2]);
                FMA2(acc[j][3], wp, vb.y, acc[j][3]);
            }
        }
        k4 = kn;
    }
#pragma unroll
    for (int j = 0; j < 4; ++j) {
        int m = lane + 32 * j;
        unsigned long long* zp = (unsigned long long*)&zpart[(warp * 128 + m) * NBATCH];
#pragma unroll
        for (int p = 0; p < 4; ++p) zp[p] = acc[j][p];
    }
}

__device__ __forceinline__ void gemv_reduce(const float* __restrict__ zpart,
                                            const float* __restrict__ bias,
                                            float* __restrict__ z) {
    const int tid = threadIdx.x;
    const int m = tid >> 1, q = tid & 1;
    float b = bias[m];
    float4 acc = make_float4(b, b, b, b);
#pragma unroll
    for (int w = 0; w < 8; ++w) {
        float4 p = *(const float4*)&zpart[(w * 128 + m) * NBATCH + q * 4];
        acc.x += p.x; acc.y += p.y; acc.z += p.z; acc.w += p.w;
    }
    *(float4*)&z[m * NBATCH + q * 4] = acc;
}

__device__ __forceinline__ float cell_update(const float* __restrict__ z,
                                             float* __restrict__ c_s,
                                             float* __restrict__ hloc) {
    const int tid = threadIdx.x;
    const int u = tid >> 3, b = tid & 7;
    float zi = z[(u)      * NBATCH + b];
    float zf = z[(32 + u) * NBATCH + b];
    float zg = z[(64 + u) * NBATCH + b];
    float zo = z[(96 + u) * NBATCH + b];
    float c  = sigm(zf) * c_s[tid] + sigm(zi) * tanhf(zg);
    c_s[tid] = c;
    float h  = sigm(zo) * tanhf(c);
    hloc[u * 8 + b] = h;
    return h;
}

extern __shared__ char smem_raw[];

__global__ void __launch_bounds__(RNN_THREADS, 1)
rnn_kernel(const float* __restrict__ cg,   // [B, U, A]
           const float* __restrict__ Ww,   // [30, 256]
           const float* __restrict__ bw)   // [30]
{
    SmemR* s = (SmemR*)smem_raw;
    const int tid = threadIdx.x;
    const int g   = blockIdx.x >> 3;     // batch group 0..15
    const int r   = blockIdx.x & 7;      // gate slice 0..7
    const int b0  = g * NBATCH;

    // ---- init ----
    for (int i = tid; i < 30 * 32; i += RNN_THREADS) {
        int o = i >> 5, u = i & 31;
        s->WwS[o * 33 + u] = Ww[o * 256 + r * UNITS + u];
    }
    if (tid < 32) s->bws[tid] = (tid < 30) ? bw[tid] : 0.0f;
    if (tid < 128) {
        s->b1s[tid] = g_B[(0 * NSLICE + r) * 128 + tid];
        s->b2s[tid] = g_B[(1 * NSLICE + r) * 128 + tid];
        s->b3s[tid] = g_B[(2 * NSLICE + r) * 128 + tid];
    }
    for (int i = tid; i < UDIM * 64; i += RNN_THREADS) {
        int u = i >> 6, q = i & 63, b = q >> 3, a = q & 7;
        s->cm[i] = cg[(size_t)(b0 + b) * (UDIM * ADIM) + u * ADIM + (r * 8 + a)];
    }
    s->c1[tid] = 0.0f; s->c2[tid] = 0.0f; s->c3[tid] = 0.0f;
    if (tid < KMIX * NBATCH) s->kappas[tid] = 0.0f;

    // per-parity pointer tables (global exchange-buffer regions)
    for (int i = tid; i < 2 * NTAB; i += RNN_THREADS) {
        int pw = i / NTAB, j = i % NTAB;
        int pr = pw ^ 1;
        int layer, k4;
        if (j < NK4_L1)                { layer = 0; k4 = j; }
        else if (j < NK4_L1 + NK4_L23) { layer = 1; k4 = j - NK4_L1; }
        else                           { layer = 2; k4 = j - NK4_L1 - NK4_L23; }
        const float* p = nullptr;                       // k4==0: patched per step
        if (k4 >= 1 && k4 < 17)  p = &g_wx[g][(k4 - 1) * 32];
        else if (k4 >= 17 && k4 < 81) {
            if (layer == 0)      p = &g_pubh[0][pr][g][(k4 - 17) * 32];
            else if (layer == 1) p = &g_pubh[0][pw][g][(k4 - 17) * 32];
            else                 p = &g_pubh[1][pw][g][(k4 - 17) * 32];
        } else if (k4 >= 81) {
            if (layer == 1)      p = &g_pubh[1][pr][g][(k4 - 81) * 32];
            else                 p = &g_pubh[2][pr][g][(k4 - 81) * 32];
        }
        s->tab[pw][j] = p;
    }
    __syncthreads();

    const float* W1 = g_W1 + r * (NK4_L1  * 512);
    const float* W2 = g_W2 + r * (NK4_L23 * 512);
    const float* W3 = g_W3 + r * (NK4_L23 * 512);

    for (int t = 0; t < T_STEPS; ++t) {
        const int pw = t & 1;

        // patch x region pointers (t-dependent) for this parity's table
        if (tid < 3) {
            const float* xp = g_xt + ((size_t)t * NGROUPS + g) * 32;
            int slot = (tid == 0) ? 0 : (tid == 1) ? NK4_L1 : (NK4_L1 + NK4_L23);
            s->tab[pw][slot] = xp;
        }
        __syncthreads();

        // ================= layer 1 =================
        gemv_ws(W1, s->tab[pw], s->zpart, NK4_L1);
        __syncthreads();
        gemv_reduce(s->zpart, s->b1s, s->z);
        __syncthreads();
        cell_update(s->z, s->c1, s->hloc);
        __syncthreads();

        // win partials over MY 32 h1 units; publish h1 slice + partials
        if (tid < 240) {
            int o = tid >> 3, b = tid & 7;
            float acc = 0.0f;
#pragma unroll 8
            for (int u = 0; u < 32; ++u)
                acc = fmaf(s->WwS[o * 33 + u], s->hloc[u * 8 + b], acc);
            s->Ploc[o * 8 + b] = acc;
        }
        if (tid < 64)
            __stcg((float4*)&g_pubh[0][pw][g][r * 256 + tid * 4],
                   ((const float4*)s->hloc)[tid]);
        __syncthreads();
        if (tid < 60)
            __stcg((float4*)&g_pwin[g][r * 240 + tid * 4],
                   ((const float4*)s->Ploc)[tid]);
        group_barrier(g, t, 0);     // site0: h1 + win partials

        // ---- attention (replicated per CTA) ----
        if (tid < 240) {
            int o = tid >> 3, b = tid & 7;
            float sum = s->bws[o];
#pragma unroll
            for (int rk = 0; rk < NSLICE; ++rk)
                sum += __ldcg(&g_pwin[g][rk * 240 + o * 8 + b]);
            s->atts[o * 8 + b] = __expf(sum);
        }
        __syncthreads();
        if (tid < KMIX * NBATCH) {
            int kk = tid >> 3, b = tid & 7;
            s->kappas[tid] += 0.1f * s->atts[(20 + kk) * 8 + b];
        }
        __syncthreads();
        for (int i = tid; i < UDIM * NBATCH; i += RNN_THREADS) {
            int u = i >> 3, b = i & 7;
            float uu = (float)u;
            float acc = 0.0f;
#pragma unroll
            for (int kk = 0; kk < KMIX; ++kk) {
                float d = s->kappas[kk * 8 + b] - uu;
                acc = fmaf(s->atts[kk * 8 + b],
                           __expf(-s->atts[(10 + kk) * 8 + b] * d * d), acc);
            }
            s->phis[i] = acc;
        }
        __syncthreads();
        if (tid < 64) {
            int b = tid >> 3, a = tid & 7;
            float acc = 0.0f;
#pragma unroll 8
            for (int u = 0; u < UDIM; ++u)
                acc = fmaf(s->phis[u * 8 + b], s->cm[u * 64 + b * 8 + a], acc);
            s->wloc[a * 8 + b] = acc;
        }
        __syncthreads();
        if (tid < 16)
            __stcg((float4*)&g_wx[g][r * 64 + tid * 4], ((const float4*)s->wloc)[tid]);
        group_barrier(g, t, 1);     // site1: w

        // ================= layer 2 =================
        gemv_ws(W2, s->tab[pw] + NK4_L1, s->zpart, NK4_L23);
        __syncthreads();
        gemv_reduce(s->zpart, s->b2s, s->z);
        __syncthreads();
        cell_update(s->z, s->c2, s->hloc);
        __syncthreads();
        if (tid < 64)
            __stcg((float4*)&g_pubh[1][pw][g][r * 256 + tid * 4],
                   ((const float4*)s->hloc)[tid]);
        group_barrier(g, t, 2);     // site2: h2

        // ================= layer 3 =================
        gemv_ws(W3, s->tab[pw] + NK4_L1 + NK4_L23, s->zpart, NK4_L23);
        __syncthreads();
        gemv_reduce(s->zpart, s->b3s, s->z);
        __syncthreads();
        {
            float h = cell_update(s->z, s->c3, s->hloc);
            int u = tid >> 3, b = tid & 7;
            g_h3buf[((size_t)t * BATCH + b0 + b) * HDIM + r * UNITS + u] = h;
        }
        __syncthreads();
        if (tid < 64)
            __stcg((float4*)&g_pubh[2][pw][g][r * 256 + tid * 4],
                   ((const float4*)s->hloc)[tid]);
        // NO barrier: consumers (L3 gemv, t+1) run after site0/1/2 of t+1;
        // every writer publishes before arriving at site0(t+1), and the
        // barrier's threadfence+atomic gives release ordering.
    }
}

// ---------------------------------------------------------------------------
// Output head
// ---------------------------------------------------------------------------
__global__ void __launch_bounds__(HEAD_THREADS)
head_kernel(float* __restrict__ out) {
    __shared__ float sh[HEAD_ROWS * HDIM];
    const int tid = threadIdx.x;
    const int r0  = blockIdx.x * HEAD_ROWS;

    for (int i = tid; i < HEAD_ROWS * HDIM; i += HEAD_THREADS)
        sh[i] = g_h3buf[(size_t)r0 * HDIM + i];
    __syncthreads();

    float acc[HEAD_ROWS];
    float bias = g_bh[tid];
#pragma unroll
    for (int r = 0; r < HEAD_ROWS; ++r) acc[r] = bias;

    for (int k = 0; k < HDIM; k += 4) {
        float w0 = g_WHt[(k + 0) * 128 + tid];
        float w1 = g_WHt[(k + 1) * 128 + tid];
        float w2 = g_WHt[(k + 2) * 128 + tid];
        float w3 = g_WHt[(k + 3) * 128 + tid];
#pragma unroll
        for (int r = 0; r < HEAD_ROWS; ++r) {
            float4 hv = *(const float4*)&sh[r * HDIM + k];
            acc[r] = fmaf(hv.x, w0, fmaf(hv.y, w1, fmaf(hv.z, w2, fmaf(hv.w, w3, acc[r]))));
        }
    }
    __syncthreads();

    float* so = sh;
    if (tid < 121) {
#pragma unroll
        for (int r = 0; r < HEAD_ROWS; ++r) so[r * 129 + tid] = acc[r];
    }
    __syncthreads();

    if (tid < HEAD_ROWS) {
        float m = -1e30f;
#pragma unroll
        for (int g = 0; g < GMIX; ++g) m = fmaxf(m, so[tid * 129 + 1 + g]);
        float e[GMIX]; float ssum = 0.0f;
#pragma unroll
        for (int g = 0; g < GMIX; ++g) { e[g] = expf(so[tid * 129 + 1 + g] - m); ssum += e[g]; }
        float inv = 1.0f / ssum;
#pragma unroll
        for (int g = 0; g < GMIX; ++g) so[tid * 129 + 1 + g] = e[g] * inv;
    }
    __syncthreads();

    const size_t TB  = (size_t)TB_ROWS;
    const size_t TBG = TB * GMIX;
    float* es  = out;
    float* pis = out + TB;
    float* mu1 = pis + TBG;
    float* mu2 = mu1 + TBG;
    float* s1  = mu2 + TBG;
    float* s2  = s1 + TBG;
    float* rho = s2 + TBG;

    if (tid < HEAD_ROWS)
        es[r0 + tid] = 1.0f / (1.0f + expf(so[tid * 129 + 0]));

    for (int idx = tid; idx < HEAD_ROWS * GMIX; idx += HEAD_THREADS) {
        int r = idx / GMIX, g = idx % GMIX;
        size_t off = (size_t)(r0 + r) * GMIX + g;
        pis[off] = so[r * 129 + 1 + g];
        mu1[off] = so[r * 129 + 21 + g];
        mu2[off] = so[r * 129 + 41 + g];
        s1[off]  = expf(so[r * 129 + 61 + g]);
        s2[off]  = expf(so[r * 129 + 81 + g]);
        rho[off] = tanhf(so[r * 129 + 101 + g]);
    }
}

// ---------------------------------------------------------------------------
// Launch
// ---------------------------------------------------------------------------
extern "C" void kernel_launch(void* const* d_in, const int* in_sizes, int n_in,
                              void* d_out, int out_size) {
    (void)in_sizes; (void)n_in; (void)out_size;
    const float* x     = (const float*)d_in[0];
    const float* cg    = (const float*)d_in[1];
    const float* W1ih  = (const float*)d_in[2];
    const float* W1hh  = (const float*)d_in[3];
    const float* b1    = (const float*)d_in[4];
    const float* W2ih  = (const float*)d_in[5];
    const float* W2hh  = (const float*)d_in[6];
    const float* b2    = (const float*)d_in[7];
    const float* W3ih  = (const float*)d_in[8];
    const float* W3hh  = (const float*)d_in[9];
    const float* b3    = (const float*)d_in[10];
    const float* Ww    = (const float*)d_in[11];
    const float* bw    = (const float*)d_in[12];
    const float* We    = (const float*)d_in[13];
    const float* be    = (const float*)d_in[14];
    const float* Wpi   = (const float*)d_in[15];
    const float* bpi   = (const float*)d_in[16];
    const float* Wm1   = (const float*)d_in[17];
    const float* bm1   = (const float*)d_in[18];
    const float* Wm2   = (const float*)d_in[19];
    const float* bm2   = (const float*)d_in[20];
    const float* Ws1   = (const float*)d_in[21];
    const float* bs1   = (const float*)d_in[22];
    const float* Ws2   = (const float*)d_in[23];
    const float* bs2   = (const float*)d_in[24];
    const float* Wr    = (const float*)d_in[25];
    const float* br    = (const float*)d_in[26];

    init_bufs_kernel<<<512, 256>>>(x);
    build_ws_kernel<<<(NSLICE * NK4_L1  * 512 + 255) / 256, 256>>>(W1ih, W1hh, NK4_L1, 0);
    build_ws_kernel<<<(NSLICE * NK4_L23 * 512 + 255) / 256, 256>>>(W2ih, W2hh, NK4_L23, 1);
    build_ws_kernel<<<(NSLICE * NK4_L23 * 512 + 255) / 256, 256>>>(W3ih, W3hh, NK4_L23, 2);
    build_bias_kernel<<<(3 * NSLICE * 128 + 255) / 256, 256>>>(b1, b2, b3);
    build_head_kernel<<<(HDIM * 128 + 255) / 256, 256>>>(We, be, Wpi, bpi, Wm1, bm1,
                                                         Wm2, bm2, Ws1, bs1, Ws2, bs2, Wr, br);

    static bool attr_set = false;
    int smem_bytes = (int)sizeof(SmemR);
    if (!attr_set) {
        cudaFuncSetAttribute(rnn_kernel, cudaFuncAttributeMaxDynamicSharedMemorySize,
                             smem_bytes);
        attr_set = true;
    }
    rnn_kernel<<<RNN_CTAS, RNN_THREADS, smem_bytes>>>(cg, Ww, bw);

    head_kernel<<<TB_ROWS / HEAD_ROWS, HEAD_THREADS>>>((float*)d_out);
}